// round 13
// baseline (speedup 1.0000x reference)
#include <cuda_runtime.h>
#include <cstdint>

#define NMAX 50000
#define EMAX 800000
#define FDIM 128
#define CDIM 40
#define SCAN_T 1024
#define STATS_B 512

// ---------------- device scratch (static allocation; no cudaMalloc) ----------
__device__ float g_xw [NMAX * FDIM];   // GEMM output of current layer
__device__ float g_h  [NMAX * FDIM];   // aggregated hidden state (pre-BN)
__device__ float g_xw3[NMAX * CDIM];   // layer-3 GEMM output
__device__ float g_deg [NMAX];         // edge-weight in-degree (without self loop)
__device__ float g_dinv[NMAX];
__device__ int   g_cnt   [NMAX];       // in-degree counts
__device__ int   g_rowptr[NMAX + 1];   // CSR row pointers (by dst)
__device__ int   g_cursor[NMAX];       // fill cursors
__device__ int2  g_csr   [EMAX];       // packed {src, bitcast(norm)}
__device__ float g_psum  [STATS_B][FDIM];   // BN partial sums   (zero-invariant:
__device__ float g_psumsq[STATS_B][FDIM];   //  bn_reduce re-zeroes after reading)
__device__ float g_scale[FDIM];
__device__ float g_shift[FDIM];

// ---------------- graph preprocessing ----------------------------------------
// edge_index is int32 (JAX x64 disabled downcasts jnp.int64 -> int32).
__global__ void k_zero(int N) {
    int i = blockIdx.x * blockDim.x + threadIdx.x;
    if (i < N) { g_deg[i] = 0.f; g_cnt[i] = 0; }
}

__global__ void k_deg_cnt(const int* __restrict__ ei,
                          const float* __restrict__ ew, int E, int N) {
    int e = blockIdx.x * blockDim.x + threadIdx.x;
    if (e >= E) return;
    int d = ei[E + e];
    if ((unsigned)d < (unsigned)N) {
        atomicAdd(&g_deg[d], ew[e]);
        atomicAdd(&g_cnt[d], 1);
    }
}

// grid-wide dinv
__global__ void k_dinv(int N) {
    int i = blockIdx.x * blockDim.x + threadIdx.x;
    if (i < N) g_dinv[i] = rsqrtf(g_deg[i] + 1.0f);   // +1 = self-loop weight
}

// single-block exclusive scan over counts -> rowptr + cursor
__global__ void k_scan(int N) {
    __shared__ int sh[SCAN_T];
    int tid = threadIdx.x;
    int chunk = (N + SCAN_T - 1) / SCAN_T;
    int start = tid * chunk;
    int end   = min(start + chunk, N);
    int sum = 0;
    for (int i = start; i < end; i++) sum += g_cnt[i];
    sh[tid] = sum;
    __syncthreads();
    for (int off = 1; off < SCAN_T; off <<= 1) {
        int v = (tid >= off) ? sh[tid - off] : 0;
        __syncthreads();
        sh[tid] += v;
        __syncthreads();
    }
    int off = sh[tid] - sum;   // exclusive prefix
    for (int i = start; i < end; i++) {
        g_rowptr[i] = off;
        g_cursor[i] = off;
        off += g_cnt[i];
    }
    if (tid == SCAN_T - 1) g_rowptr[N] = off;
}

// norm compute + CSR fill in one pass
__global__ void k_csr_build(const int* __restrict__ ei,
                            const float* __restrict__ ew, int E, int N) {
    int e = blockIdx.x * blockDim.x + threadIdx.x;
    if (e >= E) return;
    int s = ei[e];
    int d = ei[E + e];
    if ((unsigned)s >= (unsigned)N) s = 0;
    if ((unsigned)d >= (unsigned)N) d = 0;
    float nrm = g_dinv[s] * ew[e] * g_dinv[d];
    int pos = atomicAdd(&g_cursor[d], 1);
    g_csr[pos] = make_int2(s, __float_as_int(nrm));
}

// ---------------- split-precision TF32 helpers --------------------------------
__device__ __forceinline__ void split_tf32(float x, float& hi, float& lo) {
    uint32_t h;
    asm("cvt.rna.tf32.f32 %0, %1;" : "=r"(h) : "f"(x));
    hi = __uint_as_float(h);
    lo = x - hi;
}

__device__ __forceinline__ void mma_tf32(float* c, const uint32_t* a,
                                         uint32_t b0, uint32_t b1) {
    asm("mma.sync.aligned.m16n8k8.row.col.f32.tf32.tf32.f32 "
        "{%0,%1,%2,%3}, {%4,%5,%6,%7}, {%8,%9}, {%0,%1,%2,%3};"
        : "+f"(c[0]), "+f"(c[1]), "+f"(c[2]), "+f"(c[3])
        : "r"(a[0]), "r"(a[1]), "r"(a[2]), "r"(a[3]), "r"(b0), "r"(b1));
}

// ---------------- TF32 split GEMM: [M,128] @ [128,128] ------------------------
// Fragment-packed smem: each thread's m16n8k8 fragment is ONE float4 slot, so
// the inner loop issues 12 LDS.128 per 48 MMAs (was 48 scalar LDS -> L1-bound,
// R12 profile: L1 66%, tensor 34%).
//   AfH/AfL[g][s][q][tq] = {A(r,c), A(r+8,c), A(r,c+4), A(r+8,c+4)},
//        r = g*16+q, c = tq, per k8-step s of the chunk.
//   Bf[s][bn][tb]       = {Bhi(bn,k), Bhi(bn,k+4), Blo(bn,k), Blo(bn,k+4)},
//        k = s*8+tb.
#define KC 16
__global__ __launch_bounds__(256, 2) void k_gemm128_tf32(const float* __restrict__ Aext,
                                                         int bnsel,
                                                         const float* __restrict__ B,
                                                         int M) {
    const float* __restrict__ A = bnsel ? (const float*)g_h : Aext;
    __shared__ float4 AfH[8 * 2 * 8 * 4];   // 8 kB
    __shared__ float4 AfL[8 * 2 * 8 * 4];   // 8 kB
    __shared__ float4 Bf [2 * 128 * 4];     // 16 kB

    const int tid    = threadIdx.x;
    const int lane   = tid & 31;
    const int warp   = tid >> 5;
    const int warp_m = warp & 3;          // 4 x 32 rows
    const int warp_n = warp >> 2;         // 2 x 64 cols
    const int row0   = blockIdx.x * 128;

    // loader mapping (per 16-wide K chunk)
    const int a_row = tid >> 1;           // 0..127
    const int a_k0  = (tid & 1) * 8;      // 8 k values (one k8-step)
    const int b_k   = tid >> 4;           // 0..15
    const int b_n0  = (tid & 15) * 8;     // 8 n values

    // A-writer precomputed indices
    const int ag = a_row >> 4;
    const int aq = a_row & 7;
    const int au = (a_row >> 3) & 1;
    const int as = a_k0 >> 3;             // k8-step this thread stages
    float* AHp = (float*)&AfH[((ag * 2 + as) * 8 + aq) * 4];
    float* ALp = (float*)&AfL[((ag * 2 + as) * 8 + aq) * 4];

    // B-writer precomputed indices
    const int bs  = b_k >> 3;
    const int bkk = b_k & 7;
    const int btb = bkk & 3;
    const int bc  = (bkk < 4) ? 0 : 1;    // hi component (lo = +2)

    float acc[2][8][4];
#pragma unroll
    for (int mt = 0; mt < 2; mt++)
#pragma unroll
        for (int nt = 0; nt < 8; nt++)
#pragma unroll
            for (int r = 0; r < 4; r++) acc[mt][nt][r] = 0.f;

#pragma unroll 1
    for (int ch = 0; ch < 128 / KC; ch++) {
        const int k0 = ch * KC;
        __syncthreads();   // protect smem from previous iteration's readers

        // ---- stage A chunk (fused BN+ReLU when bnsel), split hi/lo ----
        {
            int grow = row0 + a_row;
            float v[8];
#pragma unroll
            for (int i = 0; i < 8; i++) v[i] = 0.f;
            if (grow < M) {
                const float* ap = A + (size_t)grow * 128 + k0 + a_k0;
                float4 u0 = *(const float4*)ap;
                float4 u1 = *(const float4*)(ap + 4);
                v[0] = u0.x; v[1] = u0.y; v[2] = u0.z; v[3] = u0.w;
                v[4] = u1.x; v[5] = u1.y; v[6] = u1.z; v[7] = u1.w;
                if (bnsel) {
#pragma unroll
                    for (int i = 0; i < 8; i++) {
                        int c = k0 + a_k0 + i;
                        v[i] = fmaxf(0.f, fmaf(v[i], g_scale[c], g_shift[c]));
                    }
                }
            }
#pragma unroll
            for (int i = 0; i < 8; i++) {
                float hi, lo;
                split_tf32(v[i], hi, lo);
                int tq   = i & 3;
                int comp = au + ((i >= 4) ? 2 : 0);
                AHp[tq * 4 + comp] = hi;
                ALp[tq * 4 + comp] = lo;
            }
        }
        // ---- stage B chunk, split hi/lo into packed fragment slots ----
        {
            const float* bp = B + (size_t)(k0 + b_k) * 128 + b_n0;
            float4 u0 = *(const float4*)bp;
            float4 u1 = *(const float4*)(bp + 4);
            float v[8] = {u0.x, u0.y, u0.z, u0.w, u1.x, u1.y, u1.z, u1.w};
#pragma unroll
            for (int i = 0; i < 8; i++) {
                float hi, lo;
                split_tf32(v[i], hi, lo);
                float* p = (float*)&Bf[(bs * 128 + (b_n0 + i)) * 4 + btb];
                p[bc]     = hi;
                p[bc + 2] = lo;
            }
        }
        __syncthreads();

        // ---- 2 k8 steps per chunk ----
#pragma unroll
        for (int s = 0; s < KC / 8; s++) {
            float4 ah[2], al[2];
#pragma unroll
            for (int mt = 0; mt < 2; mt++) {
                int g = warp_m * 2 + mt;
                int slot = ((g * 2 + s) * 8 + (lane >> 2)) * 4 + (lane & 3);
                ah[mt] = AfH[slot];
                al[mt] = AfL[slot];
            }
#pragma unroll
            for (int nt = 0; nt < 8; nt++) {
                int bn = warp_n * 64 + nt * 8 + (lane >> 2);
                float4 b4 = Bf[(s * 128 + bn) * 4 + (lane & 3)];
                uint32_t bh0 = __float_as_uint(b4.x);
                uint32_t bh1 = __float_as_uint(b4.y);
                uint32_t bl0 = __float_as_uint(b4.z);
                uint32_t bl1 = __float_as_uint(b4.w);
#pragma unroll
                for (int mt = 0; mt < 2; mt++) {
                    const uint32_t* ahp = (const uint32_t*)&ah[mt];
                    const uint32_t* alp = (const uint32_t*)&al[mt];
                    mma_tf32(acc[mt][nt], ahp, bh0, bh1);
                    mma_tf32(acc[mt][nt], ahp, bl0, bl1);
                    mma_tf32(acc[mt][nt], alp, bh0, bh1);
                }
            }
        }
    }

    // ---- epilogue: write g_xw ----
#pragma unroll
    for (int mt = 0; mt < 2; mt++) {
        int r0 = row0 + warp_m * 32 + mt * 16 + (lane >> 2);
        int r1 = r0 + 8;
#pragma unroll
        for (int nt = 0; nt < 8; nt++) {
            int col = warp_n * 64 + nt * 8 + (lane & 3) * 2;
            if (r0 < M)
                *(float2*)(g_xw + (size_t)r0 * 128 + col) =
                    make_float2(acc[mt][nt][0], acc[mt][nt][1]);
            if (r1 < M)
                *(float2*)(g_xw + (size_t)r1 * 128 + col) =
                    make_float2(acc[mt][nt][2], acc[mt][nt][3]);
        }
    }
}

// ---------------- SGEMM: [M,128] @ [128,40]  (BN2+relu(g_h) -> g_xw3) ---------
__global__ __launch_bounds__(256) void k_gemm40(const float* __restrict__ B,
                                                int M) {
    __shared__ float As[16][128];
    __shared__ float Bs[16][40];
    const int tid  = threadIdx.x;
    const int tx   = tid & 7;
    const int ty   = tid >> 3;
    const int row0 = blockIdx.x * 128;
    const int a_row = tid >> 1;
    const int a_k4  = (tid & 1) * 8;

    float acc[4][5];
#pragma unroll
    for (int i = 0; i < 4; i++)
#pragma unroll
        for (int j = 0; j < 5; j++) acc[i][j] = 0.f;

#pragma unroll 1
    for (int k0 = 0; k0 < 128; k0 += 16) {
        int grow = row0 + a_row;
        float4 av0 = make_float4(0.f, 0.f, 0.f, 0.f);
        float4 av1 = av0;
        if (grow < M) {
            const float* ap = g_h + (size_t)grow * 128 + k0 + a_k4;
            av0 = *(const float4*)ap;
            av1 = *(const float4*)(ap + 4);
            int c4 = (k0 + a_k4) >> 2;
            float4 sc0 = ((const float4*)g_scale)[c4];
            float4 sc1 = ((const float4*)g_scale)[c4 + 1];
            float4 sh0 = ((const float4*)g_shift)[c4];
            float4 sh1 = ((const float4*)g_shift)[c4 + 1];
            av0.x = fmaxf(0.f, fmaf(av0.x, sc0.x, sh0.x));
            av0.y = fmaxf(0.f, fmaf(av0.y, sc0.y, sh0.y));
            av0.z = fmaxf(0.f, fmaf(av0.z, sc0.z, sh0.z));
            av0.w = fmaxf(0.f, fmaf(av0.w, sc0.w, sh0.w));
            av1.x = fmaxf(0.f, fmaf(av1.x, sc1.x, sh1.x));
            av1.y = fmaxf(0.f, fmaf(av1.y, sc1.y, sh1.y));
            av1.z = fmaxf(0.f, fmaf(av1.z, sc1.z, sh1.z));
            av1.w = fmaxf(0.f, fmaf(av1.w, sc1.w, sh1.w));
        }
        As[a_k4 + 0][a_row] = av0.x; As[a_k4 + 1][a_row] = av0.y;
        As[a_k4 + 2][a_row] = av0.z; As[a_k4 + 3][a_row] = av0.w;
        As[a_k4 + 4][a_row] = av1.x; As[a_k4 + 5][a_row] = av1.y;
        As[a_k4 + 6][a_row] = av1.z; As[a_k4 + 7][a_row] = av1.w;

        for (int i = tid; i < 16 * 40; i += 256) {
            int bk = i / 40, bn = i % 40;
            Bs[bk][bn] = B[(size_t)(k0 + bk) * 40 + bn];
        }
        __syncthreads();

#pragma unroll
        for (int kk = 0; kk < 16; kk++) {
            float ar[4], br[5];
#pragma unroll
            for (int i = 0; i < 4; i++) ar[i] = As[kk][ty * 4 + i];
#pragma unroll
            for (int j = 0; j < 5; j++) br[j] = Bs[kk][tx * 5 + j];
#pragma unroll
            for (int i = 0; i < 4; i++)
#pragma unroll
                for (int j = 0; j < 5; j++)
                    acc[i][j] = fmaf(ar[i], br[j], acc[i][j]);
        }
        __syncthreads();
    }

#pragma unroll
    for (int i = 0; i < 4; i++) {
        int r = row0 + ty * 4 + i;
        if (r < M) {
#pragma unroll
            for (int j = 0; j < 5; j++)
                g_xw3[(size_t)r * 40 + tx * 5 + j] = acc[i][j];
        }
    }
}

// ---------------- CSR gather + fused BN partial stats -------------------------
// 8-edge unroll: 8 float4 loads in flight per warp (MLP=8) against L2 latency.
__global__ __launch_bounds__(256) void k_gather128(const float* __restrict__ b,
                                                   int N) {
    __shared__ float4 sh_s [8][32];
    __shared__ float4 sh_s2[8][32];
    const int warp = threadIdx.x >> 5;
    const int lane = threadIdx.x & 31;
    const int n = blockIdx.x * 8 + warp;

    float4 a0 = make_float4(0.f, 0.f, 0.f, 0.f);
    float4 a1 = a0, a2 = a0, a3 = a0;

    if (n < N) {
        float di = g_dinv[n]; di *= di;
        float4 bv = ((const float4*)b)[lane];
        float4 xv = ((const float4*)g_xw)[(size_t)n * 32 + lane];
        a0.x = fmaf(di, xv.x, bv.x); a0.y = fmaf(di, xv.y, bv.y);
        a0.z = fmaf(di, xv.z, bv.z); a0.w = fmaf(di, xv.w, bv.w);

        int j   = g_rowptr[n];
        int end = g_rowptr[n + 1];
        for (; j + 7 < end; j += 8) {      // MLP=8
            int2 e0 = g_csr[j],     e1 = g_csr[j + 1];
            int2 e2 = g_csr[j + 2], e3 = g_csr[j + 3];
            int2 e4 = g_csr[j + 4], e5 = g_csr[j + 5];
            int2 e6 = g_csr[j + 6], e7 = g_csr[j + 7];
            float4 v0 = ((const float4*)g_xw)[(size_t)e0.x * 32 + lane];
            float4 v1 = ((const float4*)g_xw)[(size_t)e1.x * 32 + lane];
            float4 v2 = ((const float4*)g_xw)[(size_t)e2.x * 32 + lane];
            float4 v3 = ((const float4*)g_xw)[(size_t)e3.x * 32 + lane];
            float4 v4 = ((const float4*)g_xw)[(size_t)e4.x * 32 + lane];
            float4 v5 = ((const float4*)g_xw)[(size_t)e5.x * 32 + lane];
            float4 v6 = ((const float4*)g_xw)[(size_t)e6.x * 32 + lane];
            float4 v7 = ((const float4*)g_xw)[(size_t)e7.x * 32 + lane];
            float w0 = __int_as_float(e0.y), w1 = __int_as_float(e1.y);
            float w2 = __int_as_float(e2.y), w3 = __int_as_float(e3.y);
            float w4 = __int_as_float(e4.y), w5 = __int_as_float(e5.y);
            float w6 = __int_as_float(e6.y), w7 = __int_as_float(e7.y);
            a0.x = fmaf(w0, v0.x, a0.x); a0.y = fmaf(w0, v0.y, a0.y);
            a0.z = fmaf(w0, v0.z, a0.z); a0.w = fmaf(w0, v0.w, a0.w);
            a1.x = fmaf(w1, v1.x, a1.x); a1.y = fmaf(w1, v1.y, a1.y);
            a1.z = fmaf(w1, v1.z, a1.z); a1.w = fmaf(w1, v1.w, a1.w);
            a2.x = fmaf(w2, v2.x, a2.x); a2.y = fmaf(w2, v2.y, a2.y);
            a2.z = fmaf(w2, v2.z, a2.z); a2.w = fmaf(w2, v2.w, a2.w);
            a3.x = fmaf(w3, v3.x, a3.x); a3.y = fmaf(w3, v3.y, a3.y);
            a3.z = fmaf(w3, v3.z, a3.z); a3.w = fmaf(w3, v3.w, a3.w);
            a0.x = fmaf(w4, v4.x, a0.x); a0.y = fmaf(w4, v4.y, a0.y);
            a0.z = fmaf(w4, v4.z, a0.z); a0.w = fmaf(w4, v4.w, a0.w);
            a1.x = fmaf(w5, v5.x, a1.x); a1.y = fmaf(w5, v5.y, a1.y);
            a1.z = fmaf(w5, v5.z, a1.z); a1.w = fmaf(w5, v5.w, a1.w);
            a2.x = fmaf(w6, v6.x, a2.x); a2.y = fmaf(w6, v6.y, a2.y);
            a2.z = fmaf(w6, v6.z, a2.z); a2.w = fmaf(w6, v6.w, a2.w);
            a3.x = fmaf(w7, v7.x, a3.x); a3.y = fmaf(w7, v7.y, a3.y);
            a3.z = fmaf(w7, v7.z, a3.z); a3.w = fmaf(w7, v7.w, a3.w);
        }
        for (; j < end; j++) {
            int2 e = g_csr[j];
            float4 v = ((const float4*)g_xw)[(size_t)e.x * 32 + lane];
            float w = __int_as_float(e.y);
            a0.x = fmaf(w, v.x, a0.x); a0.y = fmaf(w, v.y, a0.y);
            a0.z = fmaf(w, v.z, a0.z); a0.w = fmaf(w, v.w, a0.w);
        }
        a0.x = (a0.x + a1.x) + (a2.x + a3.x);
        a0.y = (a0.y + a1.y) + (a2.y + a3.y);
        a0.z = (a0.z + a1.z) + (a2.z + a3.z);
        a0.w = (a0.w + a1.w) + (a2.w + a3.w);
        ((float4*)g_h)[(size_t)n * 32 + lane] = a0;
    } else {
        a0 = make_float4(0.f, 0.f, 0.f, 0.f);
    }

    sh_s [warp][lane] = a0;
    sh_s2[warp][lane] = make_float4(a0.x * a0.x, a0.y * a0.y,
                                    a0.z * a0.z, a0.w * a0.w);
    __syncthreads();
    if (warp == 0) {
        float4 ts  = make_float4(0.f, 0.f, 0.f, 0.f);
        float4 ts2 = ts;
#pragma unroll
        for (int g = 0; g < 8; g++) {
            float4 s  = sh_s [g][lane];
            float4 s2 = sh_s2[g][lane];
            ts.x += s.x;  ts.y += s.y;  ts.z += s.z;  ts.w += s.w;
            ts2.x += s2.x; ts2.y += s2.y; ts2.z += s2.z; ts2.w += s2.w;
        }
        int slot = blockIdx.x & (STATS_B - 1);
        float* ps  = &g_psum  [slot][lane * 4];
        float* ps2 = &g_psumsq[slot][lane * 4];
        atomicAdd(ps + 0, ts.x);  atomicAdd(ps + 1, ts.y);
        atomicAdd(ps + 2, ts.z);  atomicAdd(ps + 3, ts.w);
        atomicAdd(ps2 + 0, ts2.x); atomicAdd(ps2 + 1, ts2.y);
        atomicAdd(ps2 + 2, ts2.z); atomicAdd(ps2 + 3, ts2.w);
    }
}

// layer 3: gather + bias + self-loop + log_softmax, one warp per node
__global__ void k_gather40_lsm(const float* __restrict__ b3,
                               float* __restrict__ out, int N) {
    int t = blockIdx.x * blockDim.x + threadIdx.x;
    int n = t >> 5, lane = t & 31;
    if (n >= N) return;
    float di = g_dinv[n]; di *= di;
    const float* xr = g_xw3 + (size_t)n * 40;
    float v1 = fmaf(di, xr[lane], b3[lane]);
    float v2 = (lane < 8) ? fmaf(di, xr[32 + lane], b3[32 + lane]) : 0.f;
    int j   = g_rowptr[n];
    int end = g_rowptr[n + 1];
    for (; j < end; j++) {
        int2 e = g_csr[j];
        float w = __int_as_float(e.y);
        const float* sr = g_xw3 + (size_t)e.x * 40;
        v1 = fmaf(w, sr[lane], v1);
        if (lane < 8) v2 = fmaf(w, sr[32 + lane], v2);
    }
    float m = (lane < 8) ? fmaxf(v1, v2) : v1;
#pragma unroll
    for (int o = 16; o > 0; o >>= 1) m = fmaxf(m, __shfl_xor_sync(0xffffffffu, m, o));
    float s = expf(v1 - m) + ((lane < 8) ? expf(v2 - m) : 0.f);
#pragma unroll
    for (int o = 16; o > 0; o >>= 1) s += __shfl_xor_sync(0xffffffffu, s, o);
    float l = m + logf(s);
    float* p = out + (size_t)n * 40;
    p[lane] = v1 - l;
    if (lane < 8) p[32 + lane] = v2 - l;
}

// ---------------- batch norm reduce (also re-zeroes partials) -----------------
__global__ void k_bn_reduce(const float* __restrict__ gamma,
                            const float* __restrict__ beta, float invN) {
    __shared__ float sh1[8][FDIM];
    __shared__ float sh2[8][FDIM];
    int col = threadIdx.x & 127;
    int grp = threadIdx.x >> 7;       // 0..7
    float s = 0.f, s2 = 0.f;
    for (int b = grp * (STATS_B / 8); b < (grp + 1) * (STATS_B / 8); b++) {
        s  += g_psum  [b][col];
        s2 += g_psumsq[b][col];
        g_psum  [b][col] = 0.f;
        g_psumsq[b][col] = 0.f;
    }
    sh1[grp][col] = s;
    sh2[grp][col] = s2;
    __syncthreads();
    if (grp == 0) {
        float ts = 0.f, ts2 = 0.f;
#pragma unroll
        for (int g = 0; g < 8; g++) { ts += sh1[g][col]; ts2 += sh2[g][col]; }
        float mean = ts * invN;
        float var  = fmaf(-mean, mean, ts2 * invN);
        float sc   = gamma[col] * rsqrtf(var + 1e-5f);
        g_scale[col] = sc;
        g_shift[col] = fmaf(-mean, sc, beta[col]);
    }
}

// ---------------- launch -----------------------------------------------------
extern "C" void kernel_launch(void* const* d_in, const int* in_sizes, int n_in,
                              void* d_out, int out_size) {
    const float* x   = (const float*)d_in[0];
    const int*   ei  = (const int*)d_in[1];     // int32 (JAX x64 disabled)
    const float* ew  = (const float*)d_in[2];
    const float* W1  = (const float*)d_in[3];
    const float* b1  = (const float*)d_in[4];
    const float* ga1 = (const float*)d_in[5];
    const float* be1 = (const float*)d_in[6];
    const float* W2  = (const float*)d_in[7];
    const float* b2  = (const float*)d_in[8];
    const float* ga2 = (const float*)d_in[9];
    const float* be2 = (const float*)d_in[10];
    const float* W3  = (const float*)d_in[11];
    const float* b3  = (const float*)d_in[12];
    float* out = (float*)d_out;

    int N = in_sizes[0] / FDIM;
    int E = in_sizes[2];

    const int TB = 256;
    int gbN  = (N + TB - 1) / TB;
    int gbE  = (E + TB - 1) / TB;
    int gbM  = (N + 127) / 128;
    int gbG  = (N + 7) / 8;                 // gather: 8 nodes / 256-thread block
    int gbNW = (N * 32 + TB - 1) / TB;      // warp-per-node

    // ---- prep + layer 1 GEMM interleaved (gemm1 at launch #4 for profiling) --
    k_zero        <<<gbN, TB>>>(N);
    k_deg_cnt     <<<gbE, TB>>>(ei, ew, E, N);
    k_dinv        <<<gbN, TB>>>(N);
    k_gemm128_tf32<<<gbM, 256>>>(x, 0, W1, N);     // launch #4 (profiled)
    k_scan        <<<1, SCAN_T>>>(N);
    k_csr_build   <<<gbE, TB>>>(ei, ew, E, N);

    // ---- layer 1 aggregation + BN ----
    k_gather128<<<gbG, 256>>>(b1, N);
    k_bn_reduce<<<1, 1024>>>(ga1, be1, 1.0f / (float)N);

    // ---- layer 2 (BN1+relu fused into gemm A-load) ----
    k_gemm128_tf32<<<gbM, 256>>>(x, 1, W2, N);
    k_gather128   <<<gbG, 256>>>(b2, N);
    k_bn_reduce   <<<1, 1024>>>(ga2, be2, 1.0f / (float)N);

    // ---- layer 3 (BN2+relu fused) + log_softmax ----
    k_gemm40       <<<gbM, 256>>>(W3, N);
    k_gather40_lsm <<<gbNW, TB>>>(b3, out, N);
}

// round 14
// speedup vs baseline: 1.1256x; 1.1256x over previous
#include <cuda_runtime.h>
#include <cstdint>

#define NMAX 50000
#define EMAX 800000
#define FDIM 128
#define CDIM 40
#define SCAN_T 1024
#define STATS_B 512

// ---------------- device scratch (static allocation; no cudaMalloc) ----------
__device__ float g_xw [NMAX * FDIM];   // GEMM output of current layer
__device__ float g_h  [NMAX * FDIM];   // aggregated hidden state (pre-BN)
__device__ float g_xw3[NMAX * CDIM];   // layer-3 GEMM output
__device__ float g_deg [NMAX];         // edge-weight in-degree (without self loop)
__device__ float g_dinv[NMAX];
__device__ int   g_cnt   [NMAX];       // in-degree counts
__device__ int   g_rowptr[NMAX + 1];   // CSR row pointers (by dst)
__device__ int   g_cursor[NMAX];       // fill cursors
__device__ int2  g_csr   [EMAX];       // packed {src, bitcast(norm)}
__device__ float g_psum  [STATS_B][FDIM];   // BN partial sums   (zero-invariant:
__device__ float g_psumsq[STATS_B][FDIM];   //  bn_reduce re-zeroes after reading)
__device__ float g_scale[FDIM];
__device__ float g_shift[FDIM];

// ---------------- graph preprocessing ----------------------------------------
// edge_index is int32 (JAX x64 disabled downcasts jnp.int64 -> int32).
__global__ void k_zero(int N) {
    int i = blockIdx.x * blockDim.x + threadIdx.x;
    if (i < N) { g_deg[i] = 0.f; g_cnt[i] = 0; }
}

__global__ void k_deg_cnt(const int* __restrict__ ei,
                          const float* __restrict__ ew, int E, int N) {
    int e = blockIdx.x * blockDim.x + threadIdx.x;
    if (e >= E) return;
    int d = ei[E + e];
    if ((unsigned)d < (unsigned)N) {
        atomicAdd(&g_deg[d], ew[e]);
        atomicAdd(&g_cnt[d], 1);
    }
}

// grid-wide dinv
__global__ void k_dinv(int N) {
    int i = blockIdx.x * blockDim.x + threadIdx.x;
    if (i < N) g_dinv[i] = rsqrtf(g_deg[i] + 1.0f);   // +1 = self-loop weight
}

// single-block exclusive scan over counts -> rowptr + cursor
__global__ void k_scan(int N) {
    __shared__ int sh[SCAN_T];
    int tid = threadIdx.x;
    int chunk = (N + SCAN_T - 1) / SCAN_T;
    int start = tid * chunk;
    int end   = min(start + chunk, N);
    int sum = 0;
    for (int i = start; i < end; i++) sum += g_cnt[i];
    sh[tid] = sum;
    __syncthreads();
    for (int off = 1; off < SCAN_T; off <<= 1) {
        int v = (tid >= off) ? sh[tid - off] : 0;
        __syncthreads();
        sh[tid] += v;
        __syncthreads();
    }
    int off = sh[tid] - sum;   // exclusive prefix
    for (int i = start; i < end; i++) {
        g_rowptr[i] = off;
        g_cursor[i] = off;
        off += g_cnt[i];
    }
    if (tid == SCAN_T - 1) g_rowptr[N] = off;
}

// norm compute + CSR fill in one pass
__global__ void k_csr_build(const int* __restrict__ ei,
                            const float* __restrict__ ew, int E, int N) {
    int e = blockIdx.x * blockDim.x + threadIdx.x;
    if (e >= E) return;
    int s = ei[e];
    int d = ei[E + e];
    if ((unsigned)s >= (unsigned)N) s = 0;
    if ((unsigned)d >= (unsigned)N) d = 0;
    float nrm = g_dinv[s] * ew[e] * g_dinv[d];
    int pos = atomicAdd(&g_cursor[d], 1);
    g_csr[pos] = make_int2(s, __float_as_int(nrm));
}

// ---------------- split-precision TF32 helpers --------------------------------
__device__ __forceinline__ void split_tf32(float x, float& hi, float& lo) {
    uint32_t h;
    asm("cvt.rna.tf32.f32 %0, %1;" : "=r"(h) : "f"(x));
    hi = __uint_as_float(h);
    lo = x - hi;
}

__device__ __forceinline__ void mma_tf32(float* c, const uint32_t* a,
                                         uint32_t b0, uint32_t b1) {
    asm("mma.sync.aligned.m16n8k8.row.col.f32.tf32.tf32.f32 "
        "{%0,%1,%2,%3}, {%4,%5,%6,%7}, {%8,%9}, {%0,%1,%2,%3};"
        : "+f"(c[0]), "+f"(c[1]), "+f"(c[2]), "+f"(c[3])
        : "r"(a[0]), "r"(a[1]), "r"(a[2]), "r"(a[3]), "r"(b0), "r"(b1));
}

// ---------------- TF32 split GEMM: [M,128] @ [128,128] ------------------------
// R12 layout (validated 51.5us): scalar-LDS staging, KPAD=17, (256,2).
// R13's fragment-packed variant REGRESSED (73.6us: long LDS.128->MMA dependency
// chains + conflicted staging stores destroyed the compiler's load pipelining).
#define KC 16
#define KPAD 17
__global__ __launch_bounds__(256, 2) void k_gemm128_tf32(const float* __restrict__ Aext,
                                                         int bnsel,
                                                         const float* __restrict__ B,
                                                         int M) {
    const float* __restrict__ A = bnsel ? (const float*)g_h : Aext;
    __shared__ float As_hi[128][KPAD];
    __shared__ float As_lo[128][KPAD];
    __shared__ float Bs_hi[128][KPAD];   // [n][k] (transposed on store)
    __shared__ float Bs_lo[128][KPAD];

    const int tid    = threadIdx.x;
    const int lane   = tid & 31;
    const int warp   = tid >> 5;
    const int warp_m = warp & 3;          // 4 x 32 rows
    const int warp_n = warp >> 2;         // 2 x 64 cols
    const int row0   = blockIdx.x * 128;

    // loader mapping (per 16-wide K chunk)
    const int a_row = tid >> 1;           // 0..127
    const int a_k0  = (tid & 1) * 8;      // two float4 = 8 k values
    const int b_k   = tid >> 4;           // 0..15
    const int b_n0  = (tid & 15) * 8;     // 8 n values (2 float4)

    float acc[2][8][4];
#pragma unroll
    for (int mt = 0; mt < 2; mt++)
#pragma unroll
        for (int nt = 0; nt < 8; nt++)
#pragma unroll
            for (int r = 0; r < 4; r++) acc[mt][nt][r] = 0.f;

#pragma unroll 1
    for (int ch = 0; ch < 128 / KC; ch++) {
        const int k0 = ch * KC;
        __syncthreads();   // protect smem from previous iteration's readers

        // ---- stage A chunk (with optional fused BN+ReLU), split hi/lo ----
        {
            int grow = row0 + a_row;
            float v[8];
#pragma unroll
            for (int i = 0; i < 8; i++) v[i] = 0.f;
            if (grow < M) {
                const float* ap = A + (size_t)grow * 128 + k0 + a_k0;
                float4 u0 = *(const float4*)ap;
                float4 u1 = *(const float4*)(ap + 4);
                v[0] = u0.x; v[1] = u0.y; v[2] = u0.z; v[3] = u0.w;
                v[4] = u1.x; v[5] = u1.y; v[6] = u1.z; v[7] = u1.w;
                if (bnsel) {
#pragma unroll
                    for (int i = 0; i < 8; i++) {
                        int c = k0 + a_k0 + i;
                        v[i] = fmaxf(0.f, fmaf(v[i], g_scale[c], g_shift[c]));
                    }
                }
            }
#pragma unroll
            for (int i = 0; i < 8; i++) {
                float hi, lo;
                split_tf32(v[i], hi, lo);
                As_hi[a_row][a_k0 + i] = hi;
                As_lo[a_row][a_k0 + i] = lo;
            }
        }
        // ---- stage B chunk transposed, split hi/lo ----
        {
            const float* bp = B + (size_t)(k0 + b_k) * 128 + b_n0;
            float4 u0 = *(const float4*)bp;
            float4 u1 = *(const float4*)(bp + 4);
            float v[8] = {u0.x, u0.y, u0.z, u0.w, u1.x, u1.y, u1.z, u1.w};
#pragma unroll
            for (int i = 0; i < 8; i++) {
                float hi, lo;
                split_tf32(v[i], hi, lo);
                Bs_hi[b_n0 + i][b_k] = hi;
                Bs_lo[b_n0 + i][b_k] = lo;
            }
        }
        __syncthreads();

        // ---- 2 k8 steps per chunk ----
#pragma unroll
        for (int s = 0; s < KC / 8; s++) {
            const int ac = s * 8 + (lane & 3);
            const int ar = warp_m * 32 + (lane >> 2);
            uint32_t a_hi[2][4], a_lo[2][4];
#pragma unroll
            for (int mt = 0; mt < 2; mt++) {
                int r = ar + mt * 16;
                a_hi[mt][0] = __float_as_uint(As_hi[r    ][ac    ]);
                a_hi[mt][1] = __float_as_uint(As_hi[r + 8][ac    ]);
                a_hi[mt][2] = __float_as_uint(As_hi[r    ][ac + 4]);
                a_hi[mt][3] = __float_as_uint(As_hi[r + 8][ac + 4]);
                a_lo[mt][0] = __float_as_uint(As_lo[r    ][ac    ]);
                a_lo[mt][1] = __float_as_uint(As_lo[r + 8][ac    ]);
                a_lo[mt][2] = __float_as_uint(As_lo[r    ][ac + 4]);
                a_lo[mt][3] = __float_as_uint(As_lo[r + 8][ac + 4]);
            }
            const int bk = s * 8 + (lane & 3);
#pragma unroll
            for (int nt = 0; nt < 8; nt++) {
                int bn = warp_n * 64 + nt * 8 + (lane >> 2);
                uint32_t bh0 = __float_as_uint(Bs_hi[bn][bk]);
                uint32_t bh1 = __float_as_uint(Bs_hi[bn][bk + 4]);
                uint32_t bl0 = __float_as_uint(Bs_lo[bn][bk]);
                uint32_t bl1 = __float_as_uint(Bs_lo[bn][bk + 4]);
#pragma unroll
                for (int mt = 0; mt < 2; mt++) {
                    mma_tf32(acc[mt][nt], a_hi[mt], bh0, bh1);
                    mma_tf32(acc[mt][nt], a_hi[mt], bl0, bl1);
                    mma_tf32(acc[mt][nt], a_lo[mt], bh0, bh1);
                }
            }
        }
    }

    // ---- epilogue: write g_xw ----
#pragma unroll
    for (int mt = 0; mt < 2; mt++) {
        int r0 = row0 + warp_m * 32 + mt * 16 + (lane >> 2);
        int r1 = r0 + 8;
#pragma unroll
        for (int nt = 0; nt < 8; nt++) {
            int col = warp_n * 64 + nt * 8 + (lane & 3) * 2;
            if (r0 < M)
                *(float2*)(g_xw + (size_t)r0 * 128 + col) =
                    make_float2(acc[mt][nt][0], acc[mt][nt][1]);
            if (r1 < M)
                *(float2*)(g_xw + (size_t)r1 * 128 + col) =
                    make_float2(acc[mt][nt][2], acc[mt][nt][3]);
        }
    }
}

// ---------------- SGEMM: [M,128] @ [128,40]  (BN2+relu(g_h) -> g_xw3) ---------
__global__ __launch_bounds__(256) void k_gemm40(const float* __restrict__ B,
                                                int M) {
    __shared__ float As[16][128];
    __shared__ float Bs[16][40];
    const int tid  = threadIdx.x;
    const int tx   = tid & 7;
    const int ty   = tid >> 3;
    const int row0 = blockIdx.x * 128;
    const int a_row = tid >> 1;
    const int a_k4  = (tid & 1) * 8;

    float acc[4][5];
#pragma unroll
    for (int i = 0; i < 4; i++)
#pragma unroll
        for (int j = 0; j < 5; j++) acc[i][j] = 0.f;

#pragma unroll 1
    for (int k0 = 0; k0 < 128; k0 += 16) {
        int grow = row0 + a_row;
        float4 av0 = make_float4(0.f, 0.f, 0.f, 0.f);
        float4 av1 = av0;
        if (grow < M) {
            const float* ap = g_h + (size_t)grow * 128 + k0 + a_k4;
            av0 = *(const float4*)ap;
            av1 = *(const float4*)(ap + 4);
            int c4 = (k0 + a_k4) >> 2;
            float4 sc0 = ((const float4*)g_scale)[c4];
            float4 sc1 = ((const float4*)g_scale)[c4 + 1];
            float4 sh0 = ((const float4*)g_shift)[c4];
            float4 sh1 = ((const float4*)g_shift)[c4 + 1];
            av0.x = fmaxf(0.f, fmaf(av0.x, sc0.x, sh0.x));
            av0.y = fmaxf(0.f, fmaf(av0.y, sc0.y, sh0.y));
            av0.z = fmaxf(0.f, fmaf(av0.z, sc0.z, sh0.z));
            av0.w = fmaxf(0.f, fmaf(av0.w, sc0.w, sh0.w));
            av1.x = fmaxf(0.f, fmaf(av1.x, sc1.x, sh1.x));
            av1.y = fmaxf(0.f, fmaf(av1.y, sc1.y, sh1.y));
            av1.z = fmaxf(0.f, fmaf(av1.z, sc1.z, sh1.z));
            av1.w = fmaxf(0.f, fmaf(av1.w, sc1.w, sh1.w));
        }
        As[a_k4 + 0][a_row] = av0.x; As[a_k4 + 1][a_row] = av0.y;
        As[a_k4 + 2][a_row] = av0.z; As[a_k4 + 3][a_row] = av0.w;
        As[a_k4 + 4][a_row] = av1.x; As[a_k4 + 5][a_row] = av1.y;
        As[a_k4 + 6][a_row] = av1.z; As[a_k4 + 7][a_row] = av1.w;

        for (int i = tid; i < 16 * 40; i += 256) {
            int bk = i / 40, bn = i % 40;
            Bs[bk][bn] = B[(size_t)(k0 + bk) * 40 + bn];
        }
        __syncthreads();

#pragma unroll
        for (int kk = 0; kk < 16; kk++) {
            float ar[4], br[5];
#pragma unroll
            for (int i = 0; i < 4; i++) ar[i] = As[kk][ty * 4 + i];
#pragma unroll
            for (int j = 0; j < 5; j++) br[j] = Bs[kk][tx * 5 + j];
#pragma unroll
            for (int i = 0; i < 4; i++)
#pragma unroll
                for (int j = 0; j < 5; j++)
                    acc[i][j] = fmaf(ar[i], br[j], acc[i][j]);
        }
        __syncthreads();
    }

#pragma unroll
    for (int i = 0; i < 4; i++) {
        int r = row0 + ty * 4 + i;
        if (r < M) {
#pragma unroll
            for (int j = 0; j < 5; j++)
                g_xw3[(size_t)r * 40 + tx * 5 + j] = acc[i][j];
        }
    }
}

// ---------------- CSR gather + fused BN partial stats -------------------------
// 8-edge unroll: 8 float4 loads in flight per warp (MLP=8) against L2 latency.
__global__ __launch_bounds__(256) void k_gather128(const float* __restrict__ b,
                                                   int N) {
    __shared__ float4 sh_s [8][32];
    __shared__ float4 sh_s2[8][32];
    const int warp = threadIdx.x >> 5;
    const int lane = threadIdx.x & 31;
    const int n = blockIdx.x * 8 + warp;

    float4 a0 = make_float4(0.f, 0.f, 0.f, 0.f);
    float4 a1 = a0, a2 = a0, a3 = a0;

    if (n < N) {
        float di = g_dinv[n]; di *= di;
        float4 bv = ((const float4*)b)[lane];
        float4 xv = ((const float4*)g_xw)[(size_t)n * 32 + lane];
        a0.x = fmaf(di, xv.x, bv.x); a0.y = fmaf(di, xv.y, bv.y);
        a0.z = fmaf(di, xv.z, bv.z); a0.w = fmaf(di, xv.w, bv.w);

        int j   = g_rowptr[n];
        int end = g_rowptr[n + 1];
        for (; j + 7 < end; j += 8) {      // MLP=8
            int2 e0 = g_csr[j],     e1 = g_csr[j + 1];
            int2 e2 = g_csr[j + 2], e3 = g_csr[j + 3];
            int2 e4 = g_csr[j + 4], e5 = g_csr[j + 5];
            int2 e6 = g_csr[j + 6], e7 = g_csr[j + 7];
            float4 v0 = ((const float4*)g_xw)[(size_t)e0.x * 32 + lane];
            float4 v1 = ((const float4*)g_xw)[(size_t)e1.x * 32 + lane];
            float4 v2 = ((const float4*)g_xw)[(size_t)e2.x * 32 + lane];
            float4 v3 = ((const float4*)g_xw)[(size_t)e3.x * 32 + lane];
            float4 v4 = ((const float4*)g_xw)[(size_t)e4.x * 32 + lane];
            float4 v5 = ((const float4*)g_xw)[(size_t)e5.x * 32 + lane];
            float4 v6 = ((const float4*)g_xw)[(size_t)e6.x * 32 + lane];
            float4 v7 = ((const float4*)g_xw)[(size_t)e7.x * 32 + lane];
            float w0 = __int_as_float(e0.y), w1 = __int_as_float(e1.y);
            float w2 = __int_as_float(e2.y), w3 = __int_as_float(e3.y);
            float w4 = __int_as_float(e4.y), w5 = __int_as_float(e5.y);
            float w6 = __int_as_float(e6.y), w7 = __int_as_float(e7.y);
            a0.x = fmaf(w0, v0.x, a0.x); a0.y = fmaf(w0, v0.y, a0.y);
            a0.z = fmaf(w0, v0.z, a0.z); a0.w = fmaf(w0, v0.w, a0.w);
            a1.x = fmaf(w1, v1.x, a1.x); a1.y = fmaf(w1, v1.y, a1.y);
            a1.z = fmaf(w1, v1.z, a1.z); a1.w = fmaf(w1, v1.w, a1.w);
            a2.x = fmaf(w2, v2.x, a2.x); a2.y = fmaf(w2, v2.y, a2.y);
            a2.z = fmaf(w2, v2.z, a2.z); a2.w = fmaf(w2, v2.w, a2.w);
            a3.x = fmaf(w3, v3.x, a3.x); a3.y = fmaf(w3, v3.y, a3.y);
            a3.z = fmaf(w3, v3.z, a3.z); a3.w = fmaf(w3, v3.w, a3.w);
            a0.x = fmaf(w4, v4.x, a0.x); a0.y = fmaf(w4, v4.y, a0.y);
            a0.z = fmaf(w4, v4.z, a0.z); a0.w = fmaf(w4, v4.w, a0.w);
            a1.x = fmaf(w5, v5.x, a1.x); a1.y = fmaf(w5, v5.y, a1.y);
            a1.z = fmaf(w5, v5.z, a1.z); a1.w = fmaf(w5, v5.w, a1.w);
            a2.x = fmaf(w6, v6.x, a2.x); a2.y = fmaf(w6, v6.y, a2.y);
            a2.z = fmaf(w6, v6.z, a2.z); a2.w = fmaf(w6, v6.w, a2.w);
            a3.x = fmaf(w7, v7.x, a3.x); a3.y = fmaf(w7, v7.y, a3.y);
            a3.z = fmaf(w7, v7.z, a3.z); a3.w = fmaf(w7, v7.w, a3.w);
        }
        for (; j < end; j++) {
            int2 e = g_csr[j];
            float4 v = ((const float4*)g_xw)[(size_t)e.x * 32 + lane];
            float w = __int_as_float(e.y);
            a0.x = fmaf(w, v.x, a0.x); a0.y = fmaf(w, v.y, a0.y);
            a0.z = fmaf(w, v.z, a0.z); a0.w = fmaf(w, v.w, a0.w);
        }
        a0.x = (a0.x + a1.x) + (a2.x + a3.x);
        a0.y = (a0.y + a1.y) + (a2.y + a3.y);
        a0.z = (a0.z + a1.z) + (a2.z + a3.z);
        a0.w = (a0.w + a1.w) + (a2.w + a3.w);
        ((float4*)g_h)[(size_t)n * 32 + lane] = a0;
    } else {
        a0 = make_float4(0.f, 0.f, 0.f, 0.f);
    }

    sh_s [warp][lane] = a0;
    sh_s2[warp][lane] = make_float4(a0.x * a0.x, a0.y * a0.y,
                                    a0.z * a0.z, a0.w * a0.w);
    __syncthreads();
    if (warp == 0) {
        float4 ts  = make_float4(0.f, 0.f, 0.f, 0.f);
        float4 ts2 = ts;
#pragma unroll
        for (int g = 0; g < 8; g++) {
            float4 s  = sh_s [g][lane];
            float4 s2 = sh_s2[g][lane];
            ts.x += s.x;  ts.y += s.y;  ts.z += s.z;  ts.w += s.w;
            ts2.x += s2.x; ts2.y += s2.y; ts2.z += s2.z; ts2.w += s2.w;
        }
        int slot = blockIdx.x & (STATS_B - 1);
        float* ps  = &g_psum  [slot][lane * 4];
        float* ps2 = &g_psumsq[slot][lane * 4];
        atomicAdd(ps + 0, ts.x);  atomicAdd(ps + 1, ts.y);
        atomicAdd(ps + 2, ts.z);  atomicAdd(ps + 3, ts.w);
        atomicAdd(ps2 + 0, ts2.x); atomicAdd(ps2 + 1, ts2.y);
        atomicAdd(ps2 + 2, ts2.z); atomicAdd(ps2 + 3, ts2.w);
    }
}

// layer 3: gather + bias + self-loop + log_softmax, one warp per node.
// 2-edge unroll (MLP=2) on the serial L2-latency chain.
__global__ void k_gather40_lsm(const float* __restrict__ b3,
                               float* __restrict__ out, int N) {
    int t = blockIdx.x * blockDim.x + threadIdx.x;
    int n = t >> 5, lane = t & 31;
    if (n >= N) return;
    float di = g_dinv[n]; di *= di;
    const float* xr = g_xw3 + (size_t)n * 40;
    float v1 = fmaf(di, xr[lane], b3[lane]);
    float v2 = (lane < 8) ? fmaf(di, xr[32 + lane], b3[32 + lane]) : 0.f;
    float u1 = 0.f, u2 = 0.f;
    int j   = g_rowptr[n];
    int end = g_rowptr[n + 1];
    for (; j + 1 < end; j += 2) {
        int2 ea = g_csr[j];
        int2 eb = g_csr[j + 1];
        float wa = __int_as_float(ea.y);
        float wb = __int_as_float(eb.y);
        const float* sa = g_xw3 + (size_t)ea.x * 40;
        const float* sb = g_xw3 + (size_t)eb.x * 40;
        v1 = fmaf(wa, sa[lane], v1);
        u1 = fmaf(wb, sb[lane], u1);
        if (lane < 8) {
            v2 = fmaf(wa, sa[32 + lane], v2);
            u2 = fmaf(wb, sb[32 + lane], u2);
        }
    }
    if (j < end) {
        int2 e = g_csr[j];
        float w = __int_as_float(e.y);
        const float* sr = g_xw3 + (size_t)e.x * 40;
        v1 = fmaf(w, sr[lane], v1);
        if (lane < 8) v2 = fmaf(w, sr[32 + lane], v2);
    }
    v1 += u1;
    v2 += u2;
    float m = (lane < 8) ? fmaxf(v1, v2) : v1;
#pragma unroll
    for (int o = 16; o > 0; o >>= 1) m = fmaxf(m, __shfl_xor_sync(0xffffffffu, m, o));
    float s = expf(v1 - m) + ((lane < 8) ? expf(v2 - m) : 0.f);
#pragma unroll
    for (int o = 16; o > 0; o >>= 1) s += __shfl_xor_sync(0xffffffffu, s, o);
    float l = m + logf(s);
    float* p = out + (size_t)n * 40;
    p[lane] = v1 - l;
    if (lane < 8) p[32 + lane] = v2 - l;
}

// ---------------- batch norm reduce (also re-zeroes partials) -----------------
__global__ void k_bn_reduce(const float* __restrict__ gamma,
                            const float* __restrict__ beta, float invN) {
    __shared__ float sh1[8][FDIM];
    __shared__ float sh2[8][FDIM];
    int col = threadIdx.x & 127;
    int grp = threadIdx.x >> 7;       // 0..7
    float s = 0.f, s2 = 0.f;
    for (int b = grp * (STATS_B / 8); b < (grp + 1) * (STATS_B / 8); b++) {
        s  += g_psum  [b][col];
        s2 += g_psumsq[b][col];
        g_psum  [b][col] = 0.f;
        g_psumsq[b][col] = 0.f;
    }
    sh1[grp][col] = s;
    sh2[grp][col] = s2;
    __syncthreads();
    if (grp == 0) {
        float ts = 0.f, ts2 = 0.f;
#pragma unroll
        for (int g = 0; g < 8; g++) { ts += sh1[g][col]; ts2 += sh2[g][col]; }
        float mean = ts * invN;
        float var  = fmaf(-mean, mean, ts2 * invN);
        float sc   = gamma[col] * rsqrtf(var + 1e-5f);
        g_scale[col] = sc;
        g_shift[col] = fmaf(-mean, sc, beta[col]);
    }
}

// ---------------- launch -----------------------------------------------------
extern "C" void kernel_launch(void* const* d_in, const int* in_sizes, int n_in,
                              void* d_out, int out_size) {
    const float* x   = (const float*)d_in[0];
    const int*   ei  = (const int*)d_in[1];     // int32 (JAX x64 disabled)
    const float* ew  = (const float*)d_in[2];
    const float* W1  = (const float*)d_in[3];
    const float* b1  = (const float*)d_in[4];
    const float* ga1 = (const float*)d_in[5];
    const float* be1 = (const float*)d_in[6];
    const float* W2  = (const float*)d_in[7];
    const float* b2  = (const float*)d_in[8];
    const float* ga2 = (const float*)d_in[9];
    const float* be2 = (const float*)d_in[10];
    const float* W3  = (const float*)d_in[11];
    const float* b3  = (const float*)d_in[12];
    float* out = (float*)d_out;

    int N = in_sizes[0] / FDIM;
    int E = in_sizes[2];

    const int TB = 256;
    int gbN  = (N + TB - 1) / TB;
    int gbE  = (E + TB - 1) / TB;
    int gbM  = (N + 127) / 128;
    int gbG  = (N + 7) / 8;                 // gather: 8 nodes / 256-thread block
    int gbNW = (N * 32 + TB - 1) / TB;      // warp-per-node

    // ---- prep + layer 1 GEMM interleaved (gemm1 at launch #4 for profiling) --
    k_zero        <<<gbN, TB>>>(N);
    k_deg_cnt     <<<gbE, TB>>>(ei, ew, E, N);
    k_dinv        <<<gbN, TB>>>(N);
    k_gemm128_tf32<<<gbM, 256>>>(x, 0, W1, N);     // launch #4 (profiled)
    k_scan        <<<1, SCAN_T>>>(N);
    k_csr_build   <<<gbE, TB>>>(ei, ew, E, N);

    // ---- layer 1 aggregation + BN ----
    k_gather128<<<gbG, 256>>>(b1, N);
    k_bn_reduce<<<1, 1024>>>(ga1, be1, 1.0f / (float)N);

    // ---- layer 2 (BN1+relu fused into gemm A-load) ----
    k_gemm128_tf32<<<gbM, 256>>>(x, 1, W2, N);
    k_gather128   <<<gbG, 256>>>(b2, N);
    k_bn_reduce   <<<1, 1024>>>(ga2, be2, 1.0f / (float)N);

    // ---- layer 3 (BN2+relu fused) + log_softmax ----
    k_gemm40       <<<gbM, 256>>>(W3, N);
    k_gather40_lsm <<<gbNW, TB>>>(b3, out, N);
}